// round 11
// baseline (speedup 1.0000x reference)
#include <cuda_runtime.h>
#include <cuda_fp16.h>

#define N_NODES 100000
#define N_EDGES 1600000
#define F_IN    128
#define HID     128
#define N_CLS   40
#define NBLK_SCAN 98
#define G1A_BLOCKS 782        // rows 0..50047
#define G1B_BLOCKS 781        // rows 50048..99999
#define COUNT_BLOCKS 12500    // 1.6M / 128

// ---------------- scratch (static device globals; zero-initialized) ------------
__device__ int    g_cnt[N_NODES];
__device__ int    g_rowptr[N_NODES + 1];
__device__ int    g_cursor[N_NODES];
__device__ float  g_dinv[N_NODES];
__device__ int    g_bsum[NBLK_SCAN];
__device__ int    g_col[N_EDGES];
__device__ __half g_H  [(size_t)N_NODES * HID];    // X@W1 (unscaled, fp16)
__device__ float  g_H1 [(size_t)N_NODES * HID];    // relu(agg1 + b1), fp32
__device__ __half g_Hs2[(size_t)N_NODES * N_CLS];  // (H1@W2)*dinv[row], fp16

// ---------------- fp32x2 packed-math helpers ----------------
__device__ __forceinline__ unsigned long long pack2(float x) {
    unsigned long long r;
    asm("mov.b64 %0, {%1, %1};" : "=l"(r) : "f"(x));
    return r;
}
__device__ __forceinline__ void fma2(unsigned long long& d, unsigned long long a,
                                     unsigned long long b) {
    asm("fma.rn.f32x2 %0, %1, %2, %0;" : "+l"(d) : "l"(a), "l"(b));
}
__device__ __forceinline__ unsigned long long mul2(unsigned long long a,
                                                   unsigned long long b) {
    unsigned long long r;
    asm("mul.rn.f32x2 %0, %1, %2;" : "=l"(r) : "l"(a), "l"(b));
    return r;
}
__device__ __forceinline__ void unpack2(unsigned long long v, float& lo, float& hi) {
    asm("mov.b64 {%0, %1}, %2;" : "=f"(lo), "=f"(hi) : "l"(v));
}

// ---------------- GEMM1 body: 64 rows x 128 cols per block ---------------------
__device__ __forceinline__ void gemm1_body(const float* __restrict__ X,
                                           const float* __restrict__ W,
                                           int row0,
                                           float (&sX)[64][33], float (&sW)[32][128]) {
    int t  = threadIdx.x;
    int rg = t & 15;
    int cg = t >> 4;

    unsigned long long acc[4][8];
#pragma unroll
    for (int i = 0; i < 4; i++)
#pragma unroll
        for (int j = 0; j < 8; j++) acc[i][j] = 0ull;

    for (int k0 = 0; k0 < F_IN; k0 += 32) {
#pragma unroll
        for (int i = 0; i < 4; i++) {
            int f = t + i * 128;
            int r = f >> 3, c = (f & 7) << 2;
            float4 v = make_float4(0.f, 0.f, 0.f, 0.f);
            if (row0 + r < N_NODES)
                v = *(const float4*)(X + (size_t)(row0 + r) * F_IN + k0 + c);
            sX[r][c] = v.x; sX[r][c + 1] = v.y; sX[r][c + 2] = v.z; sX[r][c + 3] = v.w;
        }
#pragma unroll
        for (int i = 0; i < 8; i++) {
            int f = t + i * 128;
            int r = f >> 5, c = (f & 31) << 2;
            *(float4*)&sW[r][c] = *(const float4*)(W + (size_t)(k0 + r) * HID + c);
        }
        __syncthreads();
#pragma unroll 4
        for (int kk = 0; kk < 32; kk++) {
            unsigned long long w[8];
            const ulonglong2* wp = (const ulonglong2*)&sW[kk][cg * 16];
            ulonglong2 wv;
            wv = wp[0]; w[0] = wv.x; w[1] = wv.y;
            wv = wp[1]; w[2] = wv.x; w[3] = wv.y;
            wv = wp[2]; w[4] = wv.x; w[5] = wv.y;
            wv = wp[3]; w[6] = wv.x; w[7] = wv.y;
#pragma unroll
            for (int i = 0; i < 4; i++) {
                unsigned long long x2 = pack2(sX[rg * 4 + i][kk]);
#pragma unroll
                for (int j = 0; j < 8; j++) fma2(acc[i][j], x2, w[j]);
            }
        }
        __syncthreads();
    }
    // epilogue: fp32x2 -> half2, packed 16B stores
#pragma unroll
    for (int i = 0; i < 4; i++) {
        int row = row0 + rg * 4 + i;
        if (row < N_NODES) {
            uint4 pk[2];
            unsigned* pw = (unsigned*)pk;
#pragma unroll
            for (int j = 0; j < 8; j++) {
                float lo, hi;
                unpack2(acc[i][j], lo, hi);
                __half2 h = __floats2half2_rn(lo, hi);
                pw[j] = *(unsigned*)&h;
            }
            uint4* dst = (uint4*)(g_H + (size_t)row * HID + cg * 16);
            dst[0] = pk[0]; dst[1] = pk[1];
        }
    }
}

// ============ fat1: degree count (16/17 slots) ∥ GEMM1 rows [0, 50048) =========
__global__ void __launch_bounds__(128) fat1_kernel(const int* __restrict__ ei,
                                                   const float* __restrict__ X,
                                                   const float* __restrict__ W) {
    __shared__ float sX[64][33];
    __shared__ float sW[32][128];
    int bid = blockIdx.x;
    int r17 = bid % 17;
    if (r17 != 8) {
        int cid = (bid / 17) * 16 + (r17 > 8 ? r17 - 1 : r17);
        if (cid < COUNT_BLOCKS) {
            int e = cid * 128 + threadIdx.x;
            atomicAdd(&g_cnt[ei[N_EDGES + e]], 1);
        }
        return;
    }
    int g = bid / 17;
    if (g >= G1A_BLOCKS) return;
    gemm1_body(X, W, g * 64, sX, sW);
}

// ============ fat2: CSR fill (16/17 slots) ∥ GEMM1 rows [50048, 100000) ========
__global__ void __launch_bounds__(128) fat2_kernel(const int* __restrict__ ei,
                                                   const float* __restrict__ X,
                                                   const float* __restrict__ W) {
    __shared__ float sX[64][33];
    __shared__ float sW[32][128];
    int bid = blockIdx.x;
    int r17 = bid % 17;
    if (r17 != 8) {
        int cid = (bid / 17) * 16 + (r17 > 8 ? r17 - 1 : r17);
        if (cid < COUNT_BLOCKS) {
            int e = cid * 128 + threadIdx.x;
            int src = ei[e];
            int dst = ei[N_EDGES + e];
            int p = atomicAdd(&g_cursor[dst], 1);
            g_col[p] = src;
        }
        return;
    }
    int g = bid / 17;
    if (g >= G1B_BLOCKS) return;
    gemm1_body(X, W, 50048 + g * 64, sX, sW);
}

// ============ coalesced 2-phase scan ==========================================
__global__ void __launch_bounds__(256) scan_reduce_kernel() {
    int b = blockIdx.x, t = threadIdx.x;
    int base = b * 1024;
    int s = 0;
#pragma unroll
    for (int k = 0; k < 4; k++) {
        int i = base + t + k * 256;
        if (i < N_NODES) s += g_cnt[i];
    }
#pragma unroll
    for (int o = 16; o; o >>= 1) s += __shfl_down_sync(0xffffffffu, s, o);
    __shared__ int ws[8];
    if ((t & 31) == 0) ws[t >> 5] = s;
    __syncthreads();
    if (t < 8) {
        int v = ws[t];
#pragma unroll
        for (int o = 4; o; o >>= 1) v += __shfl_down_sync(0xffu, v, o);
        if (t == 0) g_bsum[b] = v;
    }
}

__global__ void __launch_bounds__(1024) scan_dist_kernel() {
    __shared__ int sd[1024];
    __shared__ int sb[NBLK_SCAN];
    __shared__ int soff;
    int b = blockIdx.x, t = threadIdx.x;
    if (t < NBLK_SCAN) sb[t] = g_bsum[t];
    __syncthreads();
    if (t == 0) {
        int o = 0;
        for (int j = 0; j < b; j++) o += sb[j];
        soff = o;
    }
    int i = b * 1024 + t;
    int cnt = (i < N_NODES) ? g_cnt[i] : 0;
    sd[t] = cnt;
    __syncthreads();
    for (int o = 1; o < 1024; o <<= 1) {
        int v = (t >= o) ? sd[t - o] : 0;
        __syncthreads();
        sd[t] += v;
        __syncthreads();
    }
    int incl = sd[t];
    if (i < N_NODES) {
        int rp = soff + incl - cnt;
        g_rowptr[i] = rp;
        g_cursor[i] = rp;
        g_dinv[i]   = rsqrtf((float)(cnt + 1));
        g_cnt[i]    = 0;
        if (i == N_NODES - 1) g_rowptr[N_NODES] = soff + incl;
    }
}

// ============ agg1: H1 = relu(dinv_d*(H[d]*dinv_d + sum H[s]*dinv_s) + b1) =====
// warp per node, lane owns 4 features = one uint2 (2x half2) per gather
__global__ void agg1_kernel(const float* __restrict__ b1) {
    int warp = threadIdx.x >> 5;
    int lane = threadIdx.x & 31;
    int node = blockIdx.x * 4 + warp;
    if (node >= N_NODES) return;
    int beg = g_rowptr[node], end = g_rowptr[node + 1];
    const uint2* Hp = (const uint2*)g_H;       // 32 uint2 per row
    float dvn = g_dinv[node];

    uint2 us = Hp[(size_t)node * 32 + lane];
    __half2* hs = (__half2*)&us;
    float2 f0 = __half22float2(hs[0]);
    float2 f1 = __half22float2(hs[1]);
    float4 s;
    s.x = f0.x * dvn; s.y = f0.y * dvn; s.z = f1.x * dvn; s.w = f1.y * dvn;

    int e = beg;
    for (; e + 4 <= end; e += 4) {
        int i0 = g_col[e], i1 = g_col[e + 1], i2 = g_col[e + 2], i3 = g_col[e + 3];
        float d0 = g_dinv[i0], d1 = g_dinv[i1], d2 = g_dinv[i2], d3 = g_dinv[i3];
        uint2 u0 = Hp[(size_t)i0 * 32 + lane];
        uint2 u1 = Hp[(size_t)i1 * 32 + lane];
        uint2 u2 = Hp[(size_t)i2 * 32 + lane];
        uint2 u3 = Hp[(size_t)i3 * 32 + lane];
        __half2* h0 = (__half2*)&u0; __half2* h1 = (__half2*)&u1;
        __half2* h2 = (__half2*)&u2; __half2* h3 = (__half2*)&u3;
        float2 a0 = __half22float2(h0[0]), b0 = __half22float2(h0[1]);
        float2 a1 = __half22float2(h1[0]), c1 = __half22float2(h1[1]);
        float2 a2 = __half22float2(h2[0]), c2 = __half22float2(h2[1]);
        float2 a3 = __half22float2(h3[0]), c3 = __half22float2(h3[1]);
        s.x += (a0.x * d0 + a1.x * d1) + (a2.x * d2 + a3.x * d3);
        s.y += (a0.y * d0 + a1.y * d1) + (a2.y * d2 + a3.y * d3);
        s.z += (b0.x * d0 + c1.x * d1) + (c2.x * d2 + c3.x * d3);
        s.w += (b0.y * d0 + c1.y * d1) + (c2.y * d2 + c3.y * d3);
    }
    for (; e < end; e++) {
        int ic = g_col[e];
        float dc = g_dinv[ic];
        uint2 u = Hp[(size_t)ic * 32 + lane];
        __half2* h = (__half2*)&u;
        float2 a = __half22float2(h[0]);
        float2 b = __half22float2(h[1]);
        s.x += a.x * dc; s.y += a.y * dc; s.z += b.x * dc; s.w += b.y * dc;
    }
    float4 bb = ((const float4*)b1)[lane];
    float4 o;
    o.x = fmaxf(fmaf(dvn, s.x, bb.x), 0.f);
    o.y = fmaxf(fmaf(dvn, s.y, bb.y), 0.f);
    o.z = fmaxf(fmaf(dvn, s.z, bb.z), 0.f);
    o.w = fmaxf(fmaf(dvn, s.w, bb.w), 0.f);
    ((float4*)g_H1)[(size_t)node * 32 + lane] = o;
}

// ============ GEMM2: Hs2 = (H1 @ W2)*dinv[row], fp16 out =======================
// block = 256 threads / 256 rows; thread = 4 strided rows x 10 cols; smem-staged
__global__ void __launch_bounds__(256) gemm2_kernel(const float* __restrict__ W2) {
    __shared__ float sH[256 * 33];    // [row][kk], pad 33: conflict-free
    __shared__ float sW[32 * 40];     // K-chunk of W2
    int t = threadIdx.x;
    int rg = t & 63;                  // base row within block
    int cg = t >> 6;                  // 4 col groups x 10 cols
    int row0 = blockIdx.x * 256;

    unsigned long long acc[4][5];
#pragma unroll
    for (int i = 0; i < 4; i++)
#pragma unroll
        for (int j = 0; j < 5; j++) acc[i][j] = 0ull;

    for (int k0 = 0; k0 < HID; k0 += 32) {
#pragma unroll
        for (int i = 0; i < 8; i++) {         // H1 tile 256x32 = 2048 float4
            int idx = t + i * 256;
            int r = idx >> 3, c4 = idx & 7;
            float4 v = make_float4(0.f, 0.f, 0.f, 0.f);
            if (row0 + r < N_NODES)
                v = *(const float4*)(g_H1 + (size_t)(row0 + r) * HID + k0 + c4 * 4);
            float* d = &sH[r * 33 + c4 * 4];
            d[0] = v.x; d[1] = v.y; d[2] = v.z; d[3] = v.w;
        }
#pragma unroll
        for (int i = 0; i < 2; i++) {         // W2 chunk 32x40 = 320 float4
            int idx = t + i * 256;
            if (idx < 320)
                *(float4*)&sW[idx * 4] = *(const float4*)(W2 + (size_t)k0 * N_CLS + idx * 4);
        }
        __syncthreads();
#pragma unroll 4
        for (int kk = 0; kk < 32; kk++) {
            const unsigned long long* wp =
                (const unsigned long long*)&sW[kk * 40 + cg * 10];
            unsigned long long w0 = wp[0], w1 = wp[1], w2 = wp[2], w3 = wp[3], w4 = wp[4];
#pragma unroll
            for (int i = 0; i < 4; i++) {
                unsigned long long x2 = pack2(sH[(rg + 64 * i) * 33 + kk]);
                fma2(acc[i][0], x2, w0);
                fma2(acc[i][1], x2, w1);
                fma2(acc[i][2], x2, w2);
                fma2(acc[i][3], x2, w3);
                fma2(acc[i][4], x2, w4);
            }
        }
        __syncthreads();
    }
#pragma unroll
    for (int i = 0; i < 4; i++) {
        int row = row0 + rg + 64 * i;
        if (row < N_NODES) {
            unsigned long long d2 = pack2(g_dinv[row]);
            __half2* dst = (__half2*)(g_Hs2 + (size_t)row * N_CLS + cg * 10);
#pragma unroll
            for (int j = 0; j < 5; j++) {
                float lo, hi;
                unpack2(mul2(acc[i][j], d2), lo, hi);
                dst[j] = __floats2half2_rn(lo, hi);
            }
        }
    }
}

// ============ agg2: out = dinv*(Hs2[self] + sum Hs2[col]) + b2 =================
// warp per node, lanes 0..19 own one half2 (2 features)
__global__ void agg2_kernel(const float* __restrict__ b2, float* __restrict__ out) {
    int warp = threadIdx.x >> 5;
    int lane = threadIdx.x & 31;
    int node = blockIdx.x * 8 + warp;
    if (node >= N_NODES || lane >= 20) return;
    int beg = g_rowptr[node], end = g_rowptr[node + 1];
    const __half2* H2 = (const __half2*)g_Hs2;   // 20 half2 per row
    float2 s = __half22float2(H2[(size_t)node * 20 + lane]);
    int e = beg;
    for (; e + 4 <= end; e += 4) {
        int i0 = g_col[e], i1 = g_col[e + 1], i2 = g_col[e + 2], i3 = g_col[e + 3];
        float2 a0 = __half22float2(H2[(size_t)i0 * 20 + lane]);
        float2 a1 = __half22float2(H2[(size_t)i1 * 20 + lane]);
        float2 a2 = __half22float2(H2[(size_t)i2 * 20 + lane]);
        float2 a3 = __half22float2(H2[(size_t)i3 * 20 + lane]);
        s.x += (a0.x + a1.x) + (a2.x + a3.x);
        s.y += (a0.y + a1.y) + (a2.y + a3.y);
    }
    for (; e < end; e++) {
        float2 a = __half22float2(H2[(size_t)g_col[e] * 20 + lane]);
        s.x += a.x; s.y += a.y;
    }
    float dv = g_dinv[node];
    out[(size_t)node * N_CLS + lane * 2]     = fmaf(dv, s.x, b2[lane * 2]);
    out[(size_t)node * N_CLS + lane * 2 + 1] = fmaf(dv, s.y, b2[lane * 2 + 1]);
}

// ---------------- launch ----------------
extern "C" void kernel_launch(void* const* d_in, const int* in_sizes, int n_in,
                              void* d_out, int out_size) {
    const float* x  = (const float*)d_in[0];
    const int*   ei = (const int*)  d_in[1];
    const float* W1 = (const float*)d_in[2];
    const float* b1 = (const float*)d_in[3];
    const float* W2 = (const float*)d_in[4];
    const float* b2 = (const float*)d_in[5];
    float* out = (float*)d_out;
    (void)in_sizes; (void)n_in; (void)out_size;

    fat1_kernel       <<<G1A_BLOCKS * 17, 128>>>(ei, x, W1);  // count ∥ GEMM1-A
    scan_reduce_kernel<<<NBLK_SCAN, 256>>>();
    scan_dist_kernel  <<<NBLK_SCAN, 1024>>>();
    fat2_kernel       <<<(G1B_BLOCKS + 1) * 17, 128>>>(ei, x, W1); // fill ∥ GEMM1-B
    agg1_kernel       <<<(N_NODES + 3) / 4, 128>>>(b1);
    gemm2_kernel      <<<(N_NODES + 255) / 256, 256>>>(W2);
    agg2_kernel       <<<(N_NODES + 7) / 8, 256>>>(b2, out);
}

// round 15
// speedup vs baseline: 1.2781x; 1.2781x over previous
#include <cuda_runtime.h>
#include <cuda_fp16.h>
#include <cstdint>

#define N_NODES 100000
#define N_EDGES 1600000
#define F_IN    128
#define HID     128
#define N_CLS   40
#define NBLK_SCAN 98
#define G1A_BLOCKS 782        // 64-row tiles, rows [0, 50048)
#define G1B_BLOCKS 781        // rows [50048, 100000)
#define FILL_BLOCKS 12500     // 1.6M / 128

// ---------------- scratch (static device globals; zero-initialized) ------------
__device__ int    g_cnt[N_NODES];
__device__ int    g_rowptr[N_NODES + 1];
__device__ int    g_cursor[N_NODES];
__device__ float  g_dinv[N_NODES];
__device__ int    g_bsum[NBLK_SCAN];
__device__ int    g_col[N_EDGES];
__device__ __half g_W1t[F_IN * HID];               // W1^T fp16, [n][k] row-major
__device__ __half g_H  [(size_t)N_NODES * HID];    // X@W1 (unscaled, fp16)
__device__ __half g_H1h[(size_t)N_NODES * HID];    // relu(agg1+b1), fp16
__device__ __half g_Hs2[(size_t)N_NODES * N_CLS];  // (H1@W2)*dinv, fp16

// ---------------- fp32x2 packed-math helpers ----------------
__device__ __forceinline__ unsigned long long pack2(float x) {
    unsigned long long r;
    asm("mov.b64 %0, {%1, %1};" : "=l"(r) : "f"(x));
    return r;
}
__device__ __forceinline__ void fma2(unsigned long long& d, unsigned long long a,
                                     unsigned long long b) {
    asm("fma.rn.f32x2 %0, %1, %2, %0;" : "+l"(d) : "l"(a), "l"(b));
}
__device__ __forceinline__ unsigned long long mul2(unsigned long long a,
                                                   unsigned long long b) {
    unsigned long long r;
    asm("mul.rn.f32x2 %0, %1, %2;" : "=l"(r) : "l"(a), "l"(b));
    return r;
}
__device__ __forceinline__ void unpack2(unsigned long long v, float& lo, float& hi) {
    asm("mov.b64 {%0, %1}, %2;" : "=f"(lo), "=f"(hi) : "l"(v));
}
__device__ __forceinline__ uint32_t smem_u32(const void* p) {
    uint32_t a;
    asm("{ .reg .u64 t; cvta.to.shared.u64 t, %1; cvt.u32.u64 %0, t; }"
        : "=r"(a) : "l"(p));
    return a;
}

// ============ W1 -> W1^T fp16 convert (runs first; tiny) =======================
__global__ void __launch_bounds__(128) w1cvt_kernel(const float* __restrict__ W1) {
    int b = blockIdx.x;
#pragma unroll
    for (int j = 0; j < 8; j++) {
        int e = b * 1024 + j * 128 + threadIdx.x;   // e = k*128 + n (coalesced read)
        int k = e >> 7, n = e & 127;
        g_W1t[n * 128 + k] = __float2half(W1[e]);
    }
}

// ---------------- GEMM1 MMA body: tile 64 rows x 128 cols ----------------------
// 4 warps over N (32 cols each); K chunked 64+64 through smem.
__device__ __forceinline__ void gemm1_mma_body(const float* __restrict__ X, int row0,
                                               __half* smemA, __half* smemB) {
    // smemA: [64][72] halves; smemB: [128][72] halves (also reused as C [64][136])
    int tid = threadIdx.x;
    int nw = tid >> 5, lane = tid & 31;

    float acc[4][4][4];
#pragma unroll
    for (int mf = 0; mf < 4; mf++)
#pragma unroll
        for (int nf = 0; nf < 4; nf++)
#pragma unroll
            for (int q = 0; q < 4; q++) acc[mf][nf][q] = 0.f;

    for (int kc = 0; kc < 2; kc++) {
        // A chunk: 64 rows x 64 cols, fp32 -> fp16
#pragma unroll
        for (int i = 0; i < 8; i++) {
            int idx = tid + i * 128;              // 1024 float4 groups
            int r = idx >> 4, c4 = idx & 15;
            float4 v = make_float4(0.f, 0.f, 0.f, 0.f);
            if (row0 + r < N_NODES)
                v = *(const float4*)(X + (size_t)(row0 + r) * F_IN + kc * 64 + c4 * 4);
            __half2 h0 = __floats2half2_rn(v.x, v.y);
            __half2 h1 = __floats2half2_rn(v.z, v.w);
            uint2 u; u.x = *(unsigned*)&h0; u.y = *(unsigned*)&h1;
            *(uint2*)&smemA[r * 72 + c4 * 4] = u;
        }
        // B chunk: 128 n-rows x 64 k-cols from g_W1t (1024 uint4 — FULL chunk)
#pragma unroll
        for (int i = 0; i < 8; i++) {
            int idx = tid + i * 128;              // 1024 uint4
            int n = idx >> 3, q = idx & 7;
            *(uint4*)&smemB[n * 72 + q * 8] =
                *(const uint4*)(g_W1t + n * 128 + kc * 64 + q * 8);
        }
        __syncthreads();

#pragma unroll
        for (int ks = 0; ks < 4; ks++) {
            uint32_t a[4][4];
#pragma unroll
            for (int mf = 0; mf < 4; mf++) {
                uint32_t addr = smem_u32(
                    &smemA[(mf * 16 + (lane & 15)) * 72 + ks * 16 + (lane >> 4) * 8]);
                asm volatile(
                    "ldmatrix.sync.aligned.m8n8.x4.shared.b16 {%0,%1,%2,%3}, [%4];"
                    : "=r"(a[mf][0]), "=r"(a[mf][1]), "=r"(a[mf][2]), "=r"(a[mf][3])
                    : "r"(addr));
            }
            uint32_t bf[4][2];
#pragma unroll
            for (int nf = 0; nf < 4; nf++) {
                uint32_t addr = smem_u32(
                    &smemB[(nw * 32 + nf * 8 + (lane & 7)) * 72 +
                           ks * 16 + ((lane >> 3) & 1) * 8]);
                asm volatile(
                    "ldmatrix.sync.aligned.m8n8.x2.shared.b16 {%0,%1}, [%2];"
                    : "=r"(bf[nf][0]), "=r"(bf[nf][1]) : "r"(addr));
            }
#pragma unroll
            for (int mf = 0; mf < 4; mf++)
#pragma unroll
                for (int nf = 0; nf < 4; nf++) {
                    asm volatile(
                        "mma.sync.aligned.m16n8k16.row.col.f32.f16.f16.f32 "
                        "{%0,%1,%2,%3}, {%4,%5,%6,%7}, {%8,%9}, {%0,%1,%2,%3};"
                        : "+f"(acc[mf][nf][0]), "+f"(acc[mf][nf][1]),
                          "+f"(acc[mf][nf][2]), "+f"(acc[mf][nf][3])
                        : "r"(a[mf][0]), "r"(a[mf][1]), "r"(a[mf][2]), "r"(a[mf][3]),
                          "r"(bf[nf][0]), "r"(bf[nf][1]));
                }
        }
        __syncthreads();
    }

    // epilogue: frags -> Csm (overlays smemB, stride 136 halves) -> coalesced g_H
    __half* Csm = smemB;                          // [64][136]
    int r0 = lane >> 2, cp = (lane & 3) * 2;
#pragma unroll
    for (int mf = 0; mf < 4; mf++)
#pragma unroll
        for (int nf = 0; nf < 4; nf++) {
            int col = nw * 32 + nf * 8 + cp;
            __half2 lo = __floats2half2_rn(acc[mf][nf][0], acc[mf][nf][1]);
            __half2 hi = __floats2half2_rn(acc[mf][nf][2], acc[mf][nf][3]);
            *(__half2*)&Csm[(mf * 16 + r0) * 136 + col] = lo;
            *(__half2*)&Csm[(mf * 16 + r0 + 8) * 136 + col] = hi;
        }
    __syncthreads();
#pragma unroll
    for (int i = 0; i < 8; i++) {
        int idx = tid + i * 128;                  // 1024 uint4
        int r = idx >> 4, q = idx & 15;
        int row = row0 + r;
        if (row < N_NODES)
            *(uint4*)(g_H + (size_t)row * HID + q * 8) = *(uint4*)&Csm[r * 136 + q * 8];
    }
}

// ============ fat1: degree count (16/17) ∥ GEMM1-A (1/17) ======================
__global__ void __launch_bounds__(128) fat1_kernel(const int* __restrict__ ei,
                                                   const float* __restrict__ X) {
    __shared__ __align__(16) __half smemA[64 * 72];
    __shared__ __align__(16) __half smemB[128 * 72];
    int bid = blockIdx.x;
    int r17 = bid % 17;
    if (r17 != 8) {
        int cid = (bid / 17) * 16 + (r17 > 8 ? r17 - 1 : r17);
        if (cid < FILL_BLOCKS) {
            int e = cid * 128 + threadIdx.x;
            atomicAdd(&g_cnt[ei[N_EDGES + e]], 1);
        }
        return;
    }
    int g = bid / 17;                  // 0..781
    gemm1_mma_body(X, g * 64, smemA, smemB);
}

// ============ fat2: CSR fill (16/17) ∥ GEMM1-B (1/17) ==========================
__global__ void __launch_bounds__(128) fat2_kernel(const int* __restrict__ ei,
                                                   const float* __restrict__ X) {
    __shared__ __align__(16) __half smemA[64 * 72];
    __shared__ __align__(16) __half smemB[128 * 72];
    int bid = blockIdx.x;
    int r17 = bid % 17;
    if (r17 != 8) {
        int cid = (bid / 17) * 16 + (r17 > 8 ? r17 - 1 : r17);
        if (cid < FILL_BLOCKS) {
            int e = cid * 128 + threadIdx.x;
            int src = ei[e];
            int dst = ei[N_EDGES + e];
            int p = atomicAdd(&g_cursor[dst], 1);
            g_col[p] = src;
        }
        return;
    }
    int g = bid / 17;                  // 0..781 (last tile fully OOB-guarded)
    int row0 = 50048 + g * 64;
    if (row0 >= N_NODES) return;
    gemm1_mma_body(X, row0, smemA, smemB);
}

// ============ coalesced 2-phase scan ==========================================
__global__ void __launch_bounds__(256) scan_reduce_kernel() {
    int b = blockIdx.x, t = threadIdx.x;
    int base = b * 1024;
    int s = 0;
#pragma unroll
    for (int k = 0; k < 4; k++) {
        int i = base + t + k * 256;
        if (i < N_NODES) s += g_cnt[i];
    }
#pragma unroll
    for (int o = 16; o; o >>= 1) s += __shfl_down_sync(0xffffffffu, s, o);
    __shared__ int ws[8];
    if ((t & 31) == 0) ws[t >> 5] = s;
    __syncthreads();
    if (t < 8) {
        int v = ws[t];
#pragma unroll
        for (int o = 4; o; o >>= 1) v += __shfl_down_sync(0xffu, v, o);
        if (t == 0) g_bsum[b] = v;
    }
}

__global__ void __launch_bounds__(1024) scan_dist_kernel() {
    __shared__ int sd[1024];
    __shared__ int sb[NBLK_SCAN];
    __shared__ int soff;
    int b = blockIdx.x, t = threadIdx.x;
    if (t < NBLK_SCAN) sb[t] = g_bsum[t];
    __syncthreads();
    if (t == 0) {
        int o = 0;
        for (int j = 0; j < b; j++) o += sb[j];
        soff = o;
    }
    int i = b * 1024 + t;
    int cnt = (i < N_NODES) ? g_cnt[i] : 0;
    sd[t] = cnt;
    __syncthreads();
    for (int o = 1; o < 1024; o <<= 1) {
        int v = (t >= o) ? sd[t - o] : 0;
        __syncthreads();
        sd[t] += v;
        __syncthreads();
    }
    int incl = sd[t];
    if (i < N_NODES) {
        int rp = soff + incl - cnt;
        g_rowptr[i] = rp;
        g_cursor[i] = rp;
        g_dinv[i]   = rsqrtf((float)(cnt + 1));
        g_cnt[i]    = 0;
        if (i == N_NODES - 1) g_rowptr[N_NODES] = soff + incl;
    }
}

// ============ agg1: H1 = relu(dinv_d*(H[d]*dinv_d + sum H[s]*dinv_s) + b1) =====
__global__ void agg1_kernel(const float* __restrict__ b1) {
    int warp = threadIdx.x >> 5;
    int lane = threadIdx.x & 31;
    int node = blockIdx.x * 4 + warp;
    if (node >= N_NODES) return;
    int beg = g_rowptr[node], end = g_rowptr[node + 1];
    const uint2* Hp = (const uint2*)g_H;
    float dvn = g_dinv[node];

    uint2 us = Hp[(size_t)node * 32 + lane];
    __half2* hs = (__half2*)&us;
    float2 f0 = __half22float2(hs[0]);
    float2 f1 = __half22float2(hs[1]);
    float4 s;
    s.x = f0.x * dvn; s.y = f0.y * dvn; s.z = f1.x * dvn; s.w = f1.y * dvn;

    int e = beg;
    for (; e + 4 <= end; e += 4) {
        int i0 = g_col[e], i1 = g_col[e + 1], i2 = g_col[e + 2], i3 = g_col[e + 3];
        float d0 = g_dinv[i0], d1 = g_dinv[i1], d2 = g_dinv[i2], d3 = g_dinv[i3];
        uint2 u0 = Hp[(size_t)i0 * 32 + lane];
        uint2 u1 = Hp[(size_t)i1 * 32 + lane];
        uint2 u2 = Hp[(size_t)i2 * 32 + lane];
        uint2 u3 = Hp[(size_t)i3 * 32 + lane];
        __half2* h0 = (__half2*)&u0; __half2* h1 = (__half2*)&u1;
        __half2* h2 = (__half2*)&u2; __half2* h3 = (__half2*)&u3;
        float2 a0 = __half22float2(h0[0]), b0 = __half22float2(h0[1]);
        float2 a1 = __half22float2(h1[0]), c1 = __half22float2(h1[1]);
        float2 a2 = __half22float2(h2[0]), c2 = __half22float2(h2[1]);
        float2 a3 = __half22float2(h3[0]), c3 = __half22float2(h3[1]);
        s.x += (a0.x * d0 + a1.x * d1) + (a2.x * d2 + a3.x * d3);
        s.y += (a0.y * d0 + a1.y * d1) + (a2.y * d2 + a3.y * d3);
        s.z += (b0.x * d0 + c1.x * d1) + (c2.x * d2 + c3.x * d3);
        s.w += (b0.y * d0 + c1.y * d1) + (c2.y * d2 + c3.y * d3);
    }
    for (; e < end; e++) {
        int ic = g_col[e];
        float dc = g_dinv[ic];
        uint2 u = Hp[(size_t)ic * 32 + lane];
        __half2* h = (__half2*)&u;
        float2 a = __half22float2(h[0]);
        float2 b = __half22float2(h[1]);
        s.x += a.x * dc; s.y += a.y * dc; s.z += b.x * dc; s.w += b.y * dc;
    }
    float4 bb = ((const float4*)b1)[lane];
    __half2 o0 = __floats2half2_rn(fmaxf(fmaf(dvn, s.x, bb.x), 0.f),
                                   fmaxf(fmaf(dvn, s.y, bb.y), 0.f));
    __half2 o1 = __floats2half2_rn(fmaxf(fmaf(dvn, s.z, bb.z), 0.f),
                                   fmaxf(fmaf(dvn, s.w, bb.w), 0.f));
    uint2 uo;
    uo.x = *(unsigned*)&o0; uo.y = *(unsigned*)&o1;
    ((uint2*)g_H1h)[(size_t)node * 32 + lane] = uo;
}

// ============ GEMM2: Hs2 = (H1 @ W2)*dinv[row], fp16 in/out ====================
__global__ void __launch_bounds__(256) gemm2_kernel(const float* __restrict__ W2) {
    __shared__ float sH[256 * 33];
    __shared__ float sW[32 * 40];
    int t = threadIdx.x;
    int rg = t & 63;
    int cg = t >> 6;
    int row0 = blockIdx.x * 256;

    unsigned long long acc[4][5];
#pragma unroll
    for (int i = 0; i < 4; i++)
#pragma unroll
        for (int j = 0; j < 5; j++) acc[i][j] = 0ull;

    for (int k0 = 0; k0 < HID; k0 += 32) {
#pragma unroll
        for (int i = 0; i < 4; i++) {
            int idx = t + i * 256;
            int r = idx >> 2, gq = idx & 3;
            uint4 u = make_uint4(0u, 0u, 0u, 0u);
            if (row0 + r < N_NODES)
                u = *(const uint4*)(g_H1h + (size_t)(row0 + r) * HID + k0 + gq * 8);
            __half2* hp = (__half2*)&u;
            float* d = &sH[r * 33 + gq * 8];
#pragma unroll
            for (int q = 0; q < 4; q++) {
                float2 f = __half22float2(hp[q]);
                d[2 * q] = f.x; d[2 * q + 1] = f.y;
            }
        }
#pragma unroll
        for (int i = 0; i < 2; i++) {
            int idx = t + i * 256;
            if (idx < 320)
                *(float4*)&sW[idx * 4] = *(const float4*)(W2 + (size_t)k0 * N_CLS + idx * 4);
        }
        __syncthreads();
#pragma unroll 4
        for (int kk = 0; kk < 32; kk++) {
            const unsigned long long* wp =
                (const unsigned long long*)&sW[kk * 40 + cg * 10];
            unsigned long long w0 = wp[0], w1 = wp[1], w2 = wp[2], w3 = wp[3], w4 = wp[4];
#pragma unroll
            for (int i = 0; i < 4; i++) {
                unsigned long long x2 = pack2(sH[(rg + 64 * i) * 33 + kk]);
                fma2(acc[i][0], x2, w0);
                fma2(acc[i][1], x2, w1);
                fma2(acc[i][2], x2, w2);
                fma2(acc[i][3], x2, w3);
                fma2(acc[i][4], x2, w4);
            }
        }
        __syncthreads();
    }
#pragma unroll
    for (int i = 0; i < 4; i++) {
        int row = row0 + rg + 64 * i;
        if (row < N_NODES) {
            unsigned long long d2 = pack2(g_dinv[row]);
            __half2* dst = (__half2*)(g_Hs2 + (size_t)row * N_CLS + cg * 10);
#pragma unroll
            for (int j = 0; j < 5; j++) {
                float lo, hi;
                unpack2(mul2(acc[i][j], d2), lo, hi);
                dst[j] = __floats2half2_rn(lo, hi);
            }
        }
    }
}

// ============ agg2: out = dinv*(Hs2[self] + sum Hs2[col]) + b2 =================
__global__ void agg2_kernel(const float* __restrict__ b2, float* __restrict__ out) {
    int warp = threadIdx.x >> 5;
    int lane = threadIdx.x & 31;
    int node = blockIdx.x * 8 + warp;
    if (node >= N_NODES || lane >= 20) return;
    int beg = g_rowptr[node], end = g_rowptr[node + 1];
    const __half2* H2 = (const __half2*)g_Hs2;
    float2 s = __half22float2(H2[(size_t)node * 20 + lane]);
    int e = beg;
    for (; e + 4 <= end; e += 4) {
        int i0 = g_col[e], i1 = g_col[e + 1], i2 = g_col[e + 2], i3 = g_col[e + 3];
        float2 a0 = __half22float2(H2[(size_t)i0 * 20 + lane]);
        float2 a1 = __half22float2(H2[(size_t)i1 * 20 + lane]);
        float2 a2 = __half22float2(H2[(size_t)i2 * 20 + lane]);
        float2 a3 = __half22float2(H2[(size_t)i3 * 20 + lane]);
        s.x += (a0.x + a1.x) + (a2.x + a3.x);
        s.y += (a0.y + a1.y) + (a2.y + a3.y);
    }
    for (; e < end; e++) {
        float2 a = __half22float2(H2[(size_t)g_col[e] * 20 + lane]);
        s.x += a.x; s.y += a.y;
    }
    float dv = g_dinv[node];
    out[(size_t)node * N_CLS + lane * 2]     = fmaf(dv, s.x, b2[lane * 2]);
    out[(size_t)node * N_CLS + lane * 2 + 1] = fmaf(dv, s.y, b2[lane * 2 + 1]);
}

// ---------------- launch ----------------
extern "C" void kernel_launch(void* const* d_in, const int* in_sizes, int n_in,
                              void* d_out, int out_size) {
    const float* x  = (const float*)d_in[0];
    const int*   ei = (const int*)  d_in[1];
    const float* W1 = (const float*)d_in[2];
    const float* b1 = (const float*)d_in[3];
    const float* W2 = (const float*)d_in[4];
    const float* b2 = (const float*)d_in[5];
    float* out = (float*)d_out;
    (void)in_sizes; (void)n_in; (void)out_size;

    w1cvt_kernel      <<<16, 128>>>(W1);
    fat1_kernel       <<<G1A_BLOCKS * 17, 128>>>(ei, x);      // count ∥ GEMM1-A
    scan_reduce_kernel<<<NBLK_SCAN, 256>>>();
    scan_dist_kernel  <<<NBLK_SCAN, 1024>>>();
    fat2_kernel       <<<(G1B_BLOCKS + 1) * 17, 128>>>(ei, x); // fill ∥ GEMM1-B
    agg1_kernel       <<<(N_NODES + 3) / 4, 128>>>(b1);
    gemm2_kernel      <<<(N_NODES + 255) / 256, 256>>>(W2);
    agg2_kernel       <<<(N_NODES + 7) / 8, 256>>>(b2, out);
}

// round 16
// speedup vs baseline: 1.6545x; 1.2945x over previous
#include <cuda_runtime.h>
#include <cuda_fp16.h>
#include <cstdint>

#define N_NODES 100000
#define N_EDGES 1600000
#define F_IN    128
#define HID     128
#define N_CLS   40
#define NBLK_SCAN 98
#define G1_TILES 1563         // ceil(100000/64) 64-row GEMM1 tiles
#define FILL_BLOCKS 12500     // 1.6M / 128
#define G2_TILES 1563

// ---------------- scratch (static device globals; zero-initialized) ------------
__device__ int    g_cnt[N_NODES];
__device__ int    g_rowptr[N_NODES + 1];
__device__ int    g_cursor[N_NODES];
__device__ float  g_dinv[N_NODES];
__device__ int    g_bsum[NBLK_SCAN];
__device__ int    g_col[N_EDGES];
__device__ __align__(16) __half g_Xh [(size_t)N_NODES * F_IN];   // X fp16
__device__ __align__(16) __half g_W1t[F_IN * HID];               // W1^T fp16 [n][k]
__device__ __align__(16) __half g_W2t[N_CLS * F_IN];             // W2^T fp16 [n][k]
__device__ __align__(16) __half g_H  [(size_t)N_NODES * HID];    // dinv*(X@W1) fp16
__device__ __align__(16) __half g_H1h[(size_t)N_NODES * HID];    // relu(agg1+b1) fp16
__device__ __align__(16) __half g_Hs2[(size_t)N_NODES * N_CLS];  // (H1@W2)*dinv fp16

__device__ __forceinline__ uint32_t smem_u32(const void* p) {
    uint32_t a;
    asm("{ .reg .u64 t; cvta.to.shared.u64 t, %1; cvt.u32.u64 %0, t; }"
        : "=r"(a) : "l"(p));
    return a;
}

// ============ prep: degree count ∥ fp16 conversions ============================
__global__ void __launch_bounds__(128) prep_kernel(const int* __restrict__ ei,
                                                   const float* __restrict__ X,
                                                   const float* __restrict__ W1,
                                                   const float* __restrict__ W2) {
    int b = blockIdx.x, t = threadIdx.x;
    if (b < 25000) {
        if ((b & 1) == 0) {
            int e = (b >> 1) * 128 + t;
            atomicAdd(&g_cnt[ei[N_EDGES + e]], 1);
        } else {
            int j = b >> 1;
#pragma unroll
            for (int i = 0; i < 2; i++) {
                int f4 = j * 256 + i * 128 + t;      // float4 index < 3.2M
                float4 v = ((const float4*)X)[f4];
                __half2 h0 = __floats2half2_rn(v.x, v.y);
                __half2 h1 = __floats2half2_rn(v.z, v.w);
                uint2 u; u.x = *(unsigned*)&h0; u.y = *(unsigned*)&h1;
                ((uint2*)g_Xh)[f4] = u;
            }
        }
        return;
    }
    int r = b - 25000;
    if (r < 16) {                                    // W1 -> W1^T fp16
#pragma unroll
        for (int j = 0; j < 8; j++) {
            int e = r * 1024 + j * 128 + t;          // e = k*128 + n
            int k = e >> 7, n = e & 127;
            g_W1t[n * 128 + k] = __float2half(W1[e]);
        }
    } else {                                         // W2 -> W2^T fp16
        int rb = r - 16;                             // 0..4
#pragma unroll
        for (int i = 0; i < 8; i++) {
            int j = rb * 1024 + i * 128 + t;         // j = k*40 + n
            if (j < F_IN * N_CLS) {
                int k = j / N_CLS, n = j % N_CLS;
                g_W2t[n * 128 + k] = __float2half(W2[j]);
            }
        }
    }
}

// ============ coalesced 2-phase scan ==========================================
__global__ void __launch_bounds__(256) scan_reduce_kernel() {
    int b = blockIdx.x, t = threadIdx.x;
    int base = b * 1024;
    int s = 0;
#pragma unroll
    for (int k = 0; k < 4; k++) {
        int i = base + t + k * 256;
        if (i < N_NODES) s += g_cnt[i];
    }
#pragma unroll
    for (int o = 16; o; o >>= 1) s += __shfl_down_sync(0xffffffffu, s, o);
    __shared__ int ws[8];
    if ((t & 31) == 0) ws[t >> 5] = s;
    __syncthreads();
    if (t < 8) {
        int v = ws[t];
#pragma unroll
        for (int o = 4; o; o >>= 1) v += __shfl_down_sync(0xffu, v, o);
        if (t == 0) g_bsum[b] = v;
    }
}

__global__ void __launch_bounds__(1024) scan_dist_kernel() {
    __shared__ int sd[1024];
    __shared__ int sb[NBLK_SCAN];
    __shared__ int soff;
    int b = blockIdx.x, t = threadIdx.x;
    if (t < NBLK_SCAN) sb[t] = g_bsum[t];
    __syncthreads();
    if (t == 0) {
        int o = 0;
        for (int j = 0; j < b; j++) o += sb[j];
        soff = o;
    }
    int i = b * 1024 + t;
    int cnt = (i < N_NODES) ? g_cnt[i] : 0;
    sd[t] = cnt;
    __syncthreads();
    for (int o = 1; o < 1024; o <<= 1) {
        int v = (t >= o) ? sd[t - o] : 0;
        __syncthreads();
        sd[t] += v;
        __syncthreads();
    }
    int incl = sd[t];
    if (i < N_NODES) {
        int rp = soff + incl - cnt;
        g_rowptr[i] = rp;
        g_cursor[i] = rp;
        g_dinv[i]   = rsqrtf((float)(cnt + 1));
        g_cnt[i]    = 0;
        if (i == N_NODES - 1) g_rowptr[N_NODES] = soff + incl;
    }
}

// ============ fat: CSR fill (8/9) ∥ GEMM1 w/ dinv epilogue (1/9) ===============
__global__ void __launch_bounds__(128) fat_kernel(const int* __restrict__ ei) {
    __shared__ __align__(16) __half smemA[64 * 72];
    __shared__ __align__(16) __half smemB[128 * 72];
    int bid = blockIdx.x, tid = threadIdx.x;
    int r9 = bid % 9;
    if (r9 != 4) {
        int cid = (bid / 9) * 8 + (r9 > 4 ? r9 - 1 : r9);
        if (cid < FILL_BLOCKS) {
            int e = cid * 128 + tid;
            int src = ei[e];
            int dst = ei[N_EDGES + e];
            int p = atomicAdd(&g_cursor[dst], 1);
            g_col[p] = src;
        }
        return;
    }
    int g = bid / 9;                      // 0..1562
    int row0 = g * 64;
    int nw = tid >> 5, lane = tid & 31;

    float acc[4][4][4];
#pragma unroll
    for (int mf = 0; mf < 4; mf++)
#pragma unroll
        for (int nf = 0; nf < 4; nf++)
#pragma unroll
            for (int q = 0; q < 4; q++) acc[mf][nf][q] = 0.f;

    for (int kc = 0; kc < 2; kc++) {
        // A chunk: 64 rows x 64 halves (fp16 source) = 512 uint4
#pragma unroll
        for (int i = 0; i < 4; i++) {
            int idx = tid + i * 128;
            int r = idx >> 3, q = idx & 7;
            int row = row0 + r;
            uint4 u = make_uint4(0u, 0u, 0u, 0u);
            if (row < N_NODES)
                u = *(const uint4*)(g_Xh + (size_t)row * F_IN + kc * 64 + q * 8);
            *(uint4*)&smemA[r * 72 + q * 8] = u;
        }
        // B chunk: 128 n-rows x 64 k = 1024 uint4
#pragma unroll
        for (int i = 0; i < 8; i++) {
            int idx = tid + i * 128;
            int n = idx >> 3, q = idx & 7;
            *(uint4*)&smemB[n * 72 + q * 8] =
                *(const uint4*)(g_W1t + n * 128 + kc * 64 + q * 8);
        }
        __syncthreads();
#pragma unroll
        for (int ks = 0; ks < 4; ks++) {
            uint32_t a[4][4];
#pragma unroll
            for (int mf = 0; mf < 4; mf++) {
                uint32_t addr = smem_u32(
                    &smemA[(mf * 16 + (lane & 15)) * 72 + ks * 16 + (lane >> 4) * 8]);
                asm volatile(
                    "ldmatrix.sync.aligned.m8n8.x4.shared.b16 {%0,%1,%2,%3}, [%4];"
                    : "=r"(a[mf][0]), "=r"(a[mf][1]), "=r"(a[mf][2]), "=r"(a[mf][3])
                    : "r"(addr));
            }
            uint32_t bf[4][2];
#pragma unroll
            for (int nf = 0; nf < 4; nf++) {
                uint32_t addr = smem_u32(
                    &smemB[(nw * 32 + nf * 8 + (lane & 7)) * 72 +
                           ks * 16 + ((lane >> 3) & 1) * 8]);
                asm volatile(
                    "ldmatrix.sync.aligned.m8n8.x2.shared.b16 {%0,%1}, [%2];"
                    : "=r"(bf[nf][0]), "=r"(bf[nf][1]) : "r"(addr));
            }
#pragma unroll
            for (int mf = 0; mf < 4; mf++)
#pragma unroll
                for (int nf = 0; nf < 4; nf++) {
                    asm volatile(
                        "mma.sync.aligned.m16n8k16.row.col.f32.f16.f16.f32 "
                        "{%0,%1,%2,%3}, {%4,%5,%6,%7}, {%8,%9}, {%0,%1,%2,%3};"
                        : "+f"(acc[mf][nf][0]), "+f"(acc[mf][nf][1]),
                          "+f"(acc[mf][nf][2]), "+f"(acc[mf][nf][3])
                        : "r"(a[mf][0]), "r"(a[mf][1]), "r"(a[mf][2]), "r"(a[mf][3]),
                          "r"(bf[nf][0]), "r"(bf[nf][1]));
                }
        }
        __syncthreads();
    }

    // epilogue with dinv row scaling: frags -> Csm -> coalesced g_H
    __half* Csm = smemB;                  // [64][136]
    int r0 = lane >> 2, cp = (lane & 3) * 2;
#pragma unroll
    for (int mf = 0; mf < 4; mf++) {
        int ra = row0 + mf * 16 + r0;
        int rb = ra + 8;
        float dva = (ra < N_NODES) ? g_dinv[ra] : 0.f;
        float dvb = (rb < N_NODES) ? g_dinv[rb] : 0.f;
#pragma unroll
        for (int nf = 0; nf < 4; nf++) {
            int col = nw * 32 + nf * 8 + cp;
            __half2 lo = __floats2half2_rn(acc[mf][nf][0] * dva, acc[mf][nf][1] * dva);
            __half2 hi = __floats2half2_rn(acc[mf][nf][2] * dvb, acc[mf][nf][3] * dvb);
            *(__half2*)&Csm[(mf * 16 + r0) * 136 + col] = lo;
            *(__half2*)&Csm[(mf * 16 + r0 + 8) * 136 + col] = hi;
        }
    }
    __syncthreads();
#pragma unroll
    for (int i = 0; i < 8; i++) {
        int idx = tid + i * 128;
        int r = idx >> 4, q = idx & 15;
        int row = row0 + r;
        if (row < N_NODES)
            *(uint4*)(g_H + (size_t)row * HID + q * 8) = *(uint4*)&Csm[r * 136 + q * 8];
    }
}

// ============ agg1: H1 = relu(dinv_n*(H[n] + sum H[col]) + b1), H pre-scaled ===
__global__ void agg1_kernel(const float* __restrict__ b1) {
    int warp = threadIdx.x >> 5;
    int lane = threadIdx.x & 31;
    int node = blockIdx.x * 4 + warp;
    if (node >= N_NODES) return;
    int beg = g_rowptr[node], end = g_rowptr[node + 1];
    const uint2* Hp = (const uint2*)g_H;
    float dvn = g_dinv[node];

    uint2 us = Hp[(size_t)node * 32 + lane];          // self (already dinv_n-scaled)
    __half2* hs = (__half2*)&us;
    float2 f0 = __half22float2(hs[0]);
    float2 f1 = __half22float2(hs[1]);
    float4 s; s.x = f0.x; s.y = f0.y; s.z = f1.x; s.w = f1.y;

    int e = beg;
    for (; e + 4 <= end; e += 4) {
        int i0 = g_col[e], i1 = g_col[e + 1], i2 = g_col[e + 2], i3 = g_col[e + 3];
        uint2 u0 = Hp[(size_t)i0 * 32 + lane];
        uint2 u1 = Hp[(size_t)i1 * 32 + lane];
        uint2 u2 = Hp[(size_t)i2 * 32 + lane];
        uint2 u3 = Hp[(size_t)i3 * 32 + lane];
        __half2* h0 = (__half2*)&u0; __half2* h1 = (__half2*)&u1;
        __half2* h2 = (__half2*)&u2; __half2* h3 = (__half2*)&u3;
        float2 a0 = __half22float2(h0[0]), b0 = __half22float2(h0[1]);
        float2 a1 = __half22float2(h1[0]), c1 = __half22float2(h1[1]);
        float2 a2 = __half22float2(h2[0]), c2 = __half22float2(h2[1]);
        float2 a3 = __half22float2(h3[0]), c3 = __half22float2(h3[1]);
        s.x += (a0.x + a1.x) + (a2.x + a3.x);
        s.y += (a0.y + a1.y) + (a2.y + a3.y);
        s.z += (b0.x + c1.x) + (c2.x + c3.x);
        s.w += (b0.y + c1.y) + (c2.y + c3.y);
    }
    for (; e < end; e++) {
        uint2 u = Hp[(size_t)g_col[e] * 32 + lane];
        __half2* h = (__half2*)&u;
        float2 a = __half22float2(h[0]);
        float2 b = __half22float2(h[1]);
        s.x += a.x; s.y += a.y; s.z += b.x; s.w += b.y;
    }
    float4 bb = ((const float4*)b1)[lane];
    __half2 o0 = __floats2half2_rn(fmaxf(fmaf(dvn, s.x, bb.x), 0.f),
                                   fmaxf(fmaf(dvn, s.y, bb.y), 0.f));
    __half2 o1 = __floats2half2_rn(fmaxf(fmaf(dvn, s.z, bb.z), 0.f),
                                   fmaxf(fmaf(dvn, s.w, bb.w), 0.f));
    uint2 uo; uo.x = *(unsigned*)&o0; uo.y = *(unsigned*)&o1;
    ((uint2*)g_H1h)[(size_t)node * 32 + lane] = uo;
}

// ============ GEMM2 (HMMA): Hs2 = (H1 @ W2)*dinv[row], fp16 in/out =============
// block 128 thr / 4 warps; tile 64 rows x 40 cols; warp = 16 rows
__global__ void __launch_bounds__(128) gemm2h_kernel() {
    __shared__ __align__(16) __half sA[64 * 136];
    __shared__ __align__(16) __half sB[N_CLS * 136];
    __shared__ float sDv[64];
    int tid = threadIdx.x, w = tid >> 5, lane = tid & 31;
    int row0 = blockIdx.x * 64;

    // stage A: 64 rows x 128 halves = 1024 uint4
#pragma unroll
    for (int i = 0; i < 8; i++) {
        int idx = tid + i * 128;
        int r = idx >> 4, q = idx & 15;
        int row = row0 + r;
        uint4 u = make_uint4(0u, 0u, 0u, 0u);
        if (row < N_NODES)
            u = *(const uint4*)(g_H1h + (size_t)row * HID + q * 8);
        *(uint4*)&sA[r * 136 + q * 8] = u;
    }
    // stage B: 40 x 128 halves = 640 uint4
#pragma unroll
    for (int i = 0; i < 5; i++) {
        int idx = tid + i * 128;
        int n = idx >> 4, q = idx & 15;
        *(uint4*)&sB[n * 136 + q * 8] = *(const uint4*)(g_W2t + n * 128 + q * 8);
    }
    if (tid < 64) {
        int row = row0 + tid;
        sDv[tid] = (row < N_NODES) ? g_dinv[row] : 0.f;
    }
    __syncthreads();

    float acc[5][4];
#pragma unroll
    for (int nf = 0; nf < 5; nf++)
#pragma unroll
        for (int q = 0; q < 4; q++) acc[nf][q] = 0.f;

#pragma unroll
    for (int ks = 0; ks < 8; ks++) {
        uint32_t a[4];
        uint32_t addr = smem_u32(
            &sA[(w * 16 + (lane & 15)) * 136 + ks * 16 + (lane >> 4) * 8]);
        asm volatile(
            "ldmatrix.sync.aligned.m8n8.x4.shared.b16 {%0,%1,%2,%3}, [%4];"
            : "=r"(a[0]), "=r"(a[1]), "=r"(a[2]), "=r"(a[3]) : "r"(addr));
#pragma unroll
        for (int nf = 0; nf < 5; nf++) {
            uint32_t bf0, bf1;
            uint32_t baddr = smem_u32(
                &sB[(nf * 8 + (lane & 7)) * 136 + ks * 16 + ((lane >> 3) & 1) * 8]);
            asm volatile(
                "ldmatrix.sync.aligned.m8n8.x2.shared.b16 {%0,%1}, [%2];"
                : "=r"(bf0), "=r"(bf1) : "r"(baddr));
            asm volatile(
                "mma.sync.aligned.m16n8k16.row.col.f32.f16.f16.f32 "
                "{%0,%1,%2,%3}, {%4,%5,%6,%7}, {%8,%9}, {%0,%1,%2,%3};"
                : "+f"(acc[nf][0]), "+f"(acc[nf][1]), "+f"(acc[nf][2]), "+f"(acc[nf][3])
                : "r"(a[0]), "r"(a[1]), "r"(a[2]), "r"(a[3]), "r"(bf0), "r"(bf1));
        }
    }
    __syncthreads();                       // before reusing sA as C

    __half* sC = sA;                       // [64][48]
    int r0 = lane >> 2, cp = (lane & 3) * 2;
    int ra = w * 16 + r0;
    float dva = sDv[ra], dvb = sDv[ra + 8];
#pragma unroll
    for (int nf = 0; nf < 5; nf++) {
        *(__half2*)&sC[ra * 48 + nf * 8 + cp] =
            __floats2half2_rn(acc[nf][0] * dva, acc[nf][1] * dva);
        *(__half2*)&sC[(ra + 8) * 48 + nf * 8 + cp] =
            __floats2half2_rn(acc[nf][2] * dvb, acc[nf][3] * dvb);
    }
    __syncthreads();
    // store: 64 rows x 40 halves = 320 uint4
#pragma unroll
    for (int i = 0; i < 3; i++) {
        int idx = tid + i * 128;
        if (idx < 320) {
            int r = idx / 5, q = idx % 5;
            int row = row0 + r;
            if (row < N_NODES)
                *(uint4*)(g_Hs2 + (size_t)row * N_CLS + q * 8) =
                    *(uint4*)&sC[r * 48 + q * 8];
        }
    }
}

// ============ agg2: out = dinv*(Hs2[self] + sum Hs2[col]) + b2 =================
__global__ void agg2_kernel(const float* __restrict__ b2, float* __restrict__ out) {
    int warp = threadIdx.x >> 5;
    int lane = threadIdx.x & 31;
    int node = blockIdx.x * 8 + warp;
    if (node >= N_NODES || lane >= 20) return;
    int beg = g_rowptr[node], end = g_rowptr[node + 1];
    const __half2* H2 = (const __half2*)g_Hs2;
    float2 s = __half22float2(H2[(size_t)node * 20 + lane]);
    int e = beg;
    for (; e + 4 <= end; e += 4) {
        int i0 = g_col[e], i1 = g_col[e + 1], i2 = g_col[e + 2], i3 = g_col[e + 3];
        float2 a0 = __half22float2(H2[(size_t)i0 * 20 + lane]);
        float2 a1 = __half22float2(H2[(size_t)i1 * 20 + lane]);
        float2 a2 = __half22float2(H2[(size_t)i2 * 20 + lane]);
        float2 a3 = __half22float2(H2[(size_t)i3 * 20 + lane]);
        s.x += (a0.x + a1.x) + (a2.x + a3.x);
        s.y += (a0.y + a1.y) + (a2.y + a3.y);
    }
    for (; e < end; e++) {
        float2 a = __half22float2(H2[(size_t)g_col[e] * 20 + lane]);
        s.x += a.x; s.y += a.y;
    }
    float dv = g_dinv[node];
    out[(size_t)node * N_CLS + lane * 2]     = fmaf(dv, s.x, b2[lane * 2]);
    out[(size_t)node * N_CLS + lane * 2 + 1] = fmaf(dv, s.y, b2[lane * 2 + 1]);
}

// ---------------- launch ----------------
extern "C" void kernel_launch(void* const* d_in, const int* in_sizes, int n_in,
                              void* d_out, int out_size) {
    const float* x  = (const float*)d_in[0];
    const int*   ei = (const int*)  d_in[1];
    const float* W1 = (const float*)d_in[2];
    const float* b1 = (const float*)d_in[3];
    const float* W2 = (const float*)d_in[4];
    const float* b2 = (const float*)d_in[5];
    float* out = (float*)d_out;
    (void)in_sizes; (void)n_in; (void)out_size;

    prep_kernel       <<<25021, 128>>>(ei, x, W1, W2);   // count ∥ fp16 converts
    scan_reduce_kernel<<<NBLK_SCAN, 256>>>();
    scan_dist_kernel  <<<NBLK_SCAN, 1024>>>();
    fat_kernel        <<<G1_TILES * 9, 128>>>(ei);       // fill ∥ GEMM1(+dinv)
    agg1_kernel       <<<(N_NODES + 3) / 4, 128>>>(b1);
    gemm2h_kernel     <<<G2_TILES, 128>>>();
    agg2_kernel       <<<(N_NODES + 7) / 8, 256>>>(b2, out);
}

// round 17
// speedup vs baseline: 1.7131x; 1.0354x over previous
#include <cuda_runtime.h>
#include <cuda_fp16.h>
#include <cstdint>

#define N_NODES 100000
#define N_EDGES 1600000
#define F_IN    128
#define HID     128
#define N_CLS   40
#define NBLK_SCAN 98
#define G1_TILES 1563         // ceil(100000/64) 64-row GEMM1 tiles
#define G2_TILES 1563

// ---------------- scratch (static device globals; zero-initialized) ------------
__device__ int    g_cnt[N_NODES];
__device__ int    g_rowptr[N_NODES + 1];
__device__ int    g_cursor[N_NODES];
__device__ float  g_dinv[N_NODES];
__device__ int    g_bsum[NBLK_SCAN];
__device__ int    g_col[N_EDGES];
__device__ __align__(16) __half g_Xh [(size_t)N_NODES * F_IN];   // X fp16
__device__ __align__(16) __half g_W1t[F_IN * HID];               // W1^T fp16 [n][k]
__device__ __align__(16) __half g_W2t[N_CLS * F_IN];             // W2^T fp16 [n][k]
__device__ __align__(16) __half g_H  [(size_t)N_NODES * HID];    // dinv*(X@W1) fp16
__device__ __align__(16) __half g_H1h[(size_t)N_NODES * HID];    // relu(agg1+b1) fp16
__device__ __align__(16) __half g_Hs2[(size_t)N_NODES * N_CLS];  // (H1@W2)*dinv fp16

__device__ __forceinline__ uint32_t smem_u32(const void* p) {
    uint32_t a;
    asm("{ .reg .u64 t; cvta.to.shared.u64 t, %1; cvt.u32.u64 %0, t; }"
        : "=r"(a) : "l"(p));
    return a;
}

// ============ prep: degree count ∥ fp16 conversions ============================
__global__ void __launch_bounds__(128) prep_kernel(const int* __restrict__ ei,
                                                   const float* __restrict__ X,
                                                   const float* __restrict__ W1,
                                                   const float* __restrict__ W2) {
    int b = blockIdx.x, t = threadIdx.x;
    if (b < 25000) {
        if ((b & 1) == 0) {
            int e = (b >> 1) * 128 + t;
            atomicAdd(&g_cnt[ei[N_EDGES + e]], 1);
        } else {
            int j = b >> 1;
#pragma unroll
            for (int i = 0; i < 2; i++) {
                int f4 = j * 256 + i * 128 + t;      // float4 index < 3.2M
                float4 v = ((const float4*)X)[f4];
                __half2 h0 = __floats2half2_rn(v.x, v.y);
                __half2 h1 = __floats2half2_rn(v.z, v.w);
                uint2 u; u.x = *(unsigned*)&h0; u.y = *(unsigned*)&h1;
                ((uint2*)g_Xh)[f4] = u;
            }
        }
        return;
    }
    int r = b - 25000;
    if (r < 16) {                                    // W1 -> W1^T fp16
#pragma unroll
        for (int j = 0; j < 8; j++) {
            int e = r * 1024 + j * 128 + t;          // e = k*128 + n
            int k = e >> 7, n = e & 127;
            g_W1t[n * 128 + k] = __float2half(W1[e]);
        }
    } else {                                         // W2 -> W2^T fp16
        int rb = r - 16;                             // 0..4
#pragma unroll
        for (int i = 0; i < 8; i++) {
            int j = rb * 1024 + i * 128 + t;         // j = k*40 + n
            if (j < F_IN * N_CLS) {
                int k = j / N_CLS, n = j % N_CLS;
                g_W2t[n * 128 + k] = __float2half(W2[j]);
            }
        }
    }
}

// ============ coalesced 2-phase scan ==========================================
__global__ void __launch_bounds__(256) scan_reduce_kernel() {
    int b = blockIdx.x, t = threadIdx.x;
    int base = b * 1024;
    int s = 0;
#pragma unroll
    for (int k = 0; k < 4; k++) {
        int i = base + t + k * 256;
        if (i < N_NODES) s += g_cnt[i];
    }
#pragma unroll
    for (int o = 16; o; o >>= 1) s += __shfl_down_sync(0xffffffffu, s, o);
    __shared__ int ws[8];
    if ((t & 31) == 0) ws[t >> 5] = s;
    __syncthreads();
    if (t < 8) {
        int v = ws[t];
#pragma unroll
        for (int o = 4; o; o >>= 1) v += __shfl_down_sync(0xffu, v, o);
        if (t == 0) g_bsum[b] = v;
    }
}

__global__ void __launch_bounds__(1024) scan_dist_kernel() {
    __shared__ int sd[1024];
    __shared__ int sb[NBLK_SCAN];
    __shared__ int soff;
    int b = blockIdx.x, t = threadIdx.x;
    if (t < NBLK_SCAN) sb[t] = g_bsum[t];
    __syncthreads();
    if (t == 0) {
        int o = 0;
        for (int j = 0; j < b; j++) o += sb[j];
        soff = o;
    }
    int i = b * 1024 + t;
    int cnt = (i < N_NODES) ? g_cnt[i] : 0;
    sd[t] = cnt;
    __syncthreads();
    for (int o = 1; o < 1024; o <<= 1) {
        int v = (t >= o) ? sd[t - o] : 0;
        __syncthreads();
        sd[t] += v;
        __syncthreads();
    }
    int incl = sd[t];
    if (i < N_NODES) {
        int rp = soff + incl - cnt;
        g_rowptr[i] = rp;
        g_cursor[i] = rp;
        g_dinv[i]   = rsqrtf((float)(cnt + 1));
        g_cnt[i]    = 0;
        if (i == N_NODES - 1) g_rowptr[N_NODES] = soff + incl;
    }
}

// ============ fat: CSR fill (1/2, 1024 edges/block) ∥ GEMM1+dinv (1/2) =========
__global__ void __launch_bounds__(128) fat_kernel(const int* __restrict__ ei) {
    __shared__ __align__(16) __half smemA[64 * 72];
    __shared__ __align__(16) __half smemB[128 * 72];
    int bid = blockIdx.x, tid = threadIdx.x;

    if (bid & 1) {
        // ---- fill path: 1024 edges, 8-way ILP per thread ----
        int base = (bid >> 1) * 1024 + tid;
#pragma unroll
        for (int i = 0; i < 8; i++) {
            int e = base + i * 128;
            if (e < N_EDGES) {
                int src = ei[e];
                int dst = ei[N_EDGES + e];
                int p = atomicAdd(&g_cursor[dst], 1);
                g_col[p] = src;
            }
        }
        return;
    }

    int g = bid >> 1;                     // 0..1562
    int row0 = g * 64;
    int nw = tid >> 5, lane = tid & 31;

    float acc[4][4][4];
#pragma unroll
    for (int mf = 0; mf < 4; mf++)
#pragma unroll
        for (int nf = 0; nf < 4; nf++)
#pragma unroll
            for (int q = 0; q < 4; q++) acc[mf][nf][q] = 0.f;

    for (int kc = 0; kc < 2; kc++) {
        // A chunk: 64 rows x 64 halves (fp16 source) = 512 uint4
#pragma unroll
        for (int i = 0; i < 4; i++) {
            int idx = tid + i * 128;
            int r = idx >> 3, q = idx & 7;
            int row = row0 + r;
            uint4 u = make_uint4(0u, 0u, 0u, 0u);
            if (row < N_NODES)
                u = *(const uint4*)(g_Xh + (size_t)row * F_IN + kc * 64 + q * 8);
            *(uint4*)&smemA[r * 72 + q * 8] = u;
        }
        // B chunk: 128 n-rows x 64 k = 1024 uint4
#pragma unroll
        for (int i = 0; i < 8; i++) {
            int idx = tid + i * 128;
            int n = idx >> 3, q = idx & 7;
            *(uint4*)&smemB[n * 72 + q * 8] =
                *(const uint4*)(g_W1t + n * 128 + kc * 64 + q * 8);
        }
        __syncthreads();
#pragma unroll
        for (int ks = 0; ks < 4; ks++) {
            uint32_t a[4][4];
#pragma unroll
            for (int mf = 0; mf < 4; mf++) {
                uint32_t addr = smem_u32(
                    &smemA[(mf * 16 + (lane & 15)) * 72 + ks * 16 + (lane >> 4) * 8]);
                asm volatile(
                    "ldmatrix.sync.aligned.m8n8.x4.shared.b16 {%0,%1,%2,%3}, [%4];"
                    : "=r"(a[mf][0]), "=r"(a[mf][1]), "=r"(a[mf][2]), "=r"(a[mf][3])
                    : "r"(addr));
            }
            uint32_t bf[4][2];
#pragma unroll
            for (int nf = 0; nf < 4; nf++) {
                uint32_t addr = smem_u32(
                    &smemB[(nw * 32 + nf * 8 + (lane & 7)) * 72 +
                           ks * 16 + ((lane >> 3) & 1) * 8]);
                asm volatile(
                    "ldmatrix.sync.aligned.m8n8.x2.shared.b16 {%0,%1}, [%2];"
                    : "=r"(bf[nf][0]), "=r"(bf[nf][1]) : "r"(addr));
            }
#pragma unroll
            for (int mf = 0; mf < 4; mf++)
#pragma unroll
                for (int nf = 0; nf < 4; nf++) {
                    asm volatile(
                        "mma.sync.aligned.m16n8k16.row.col.f32.f16.f16.f32 "
                        "{%0,%1,%2,%3}, {%4,%5,%6,%7}, {%8,%9}, {%0,%1,%2,%3};"
                        : "+f"(acc[mf][nf][0]), "+f"(acc[mf][nf][1]),
                          "+f"(acc[mf][nf][2]), "+f"(acc[mf][nf][3])
                        : "r"(a[mf][0]), "r"(a[mf][1]), "r"(a[mf][2]), "r"(a[mf][3]),
                          "r"(bf[nf][0]), "r"(bf[nf][1]));
                }
        }
        __syncthreads();
    }

    // epilogue with dinv row scaling: frags -> Csm -> coalesced g_H
    __half* Csm = smemB;                  // [64][136]
    int r0 = lane >> 2, cp = (lane & 3) * 2;
#pragma unroll
    for (int mf = 0; mf < 4; mf++) {
        int ra = row0 + mf * 16 + r0;
        int rb = ra + 8;
        float dva = (ra < N_NODES) ? g_dinv[ra] : 0.f;
        float dvb = (rb < N_NODES) ? g_dinv[rb] : 0.f;
#pragma unroll
        for (int nf = 0; nf < 4; nf++) {
            int col = nw * 32 + nf * 8 + cp;
            __half2 lo = __floats2half2_rn(acc[mf][nf][0] * dva, acc[mf][nf][1] * dva);
            __half2 hi = __floats2half2_rn(acc[mf][nf][2] * dvb, acc[mf][nf][3] * dvb);
            *(__half2*)&Csm[(mf * 16 + r0) * 136 + col] = lo;
            *(__half2*)&Csm[(mf * 16 + r0 + 8) * 136 + col] = hi;
        }
    }
    __syncthreads();
#pragma unroll
    for (int i = 0; i < 8; i++) {
        int idx = tid + i * 128;
        int r = idx >> 4, q = idx & 15;
        int row = row0 + r;
        if (row < N_NODES)
            *(uint4*)(g_H + (size_t)row * HID + q * 8) = *(uint4*)&Csm[r * 136 + q * 8];
    }
}

// ============ agg1: H1 = relu(dinv_n*(H[n] + sum H[col]) + b1), H pre-scaled ===
__global__ void agg1_kernel(const float* __restrict__ b1) {
    int warp = threadIdx.x >> 5;
    int lane = threadIdx.x & 31;
    int node = blockIdx.x * 4 + warp;
    if (node >= N_NODES) return;
    int beg = g_rowptr[node], end = g_rowptr[node + 1];
    const uint2* Hp = (const uint2*)g_H;
    float dvn = g_dinv[node];

    uint2 us = Hp[(size_t)node * 32 + lane];          // self (already dinv_n-scaled)
    __half2* hs = (__half2*)&us;
    float2 f0 = __half22float2(hs[0]);
    float2 f1 = __half22float2(hs[1]);
    float4 s; s.x = f0.x; s.y = f0.y; s.z = f1.x; s.w = f1.y;

    int e = beg;
    for (; e + 4 <= end; e += 4) {
        int i0 = g_col[e], i1 = g_col[e + 1], i2 = g_col[e + 2], i3 = g_col[e + 3];
        uint2 u0 = Hp[(size_t)i0 * 32 + lane];
        uint2 u1 = Hp[(size_t)i1 * 32 + lane];
        uint2 u2 = Hp[(size_t)i2 * 32 + lane];
        uint2 u3 = Hp[(size_t)i3 * 32 + lane];
        __half2* h0 = (__half2*)&u0; __half2* h1 = (__half2*)&u1;
        __half2* h2 = (__half2*)&u2; __half2* h3 = (__half2*)&u3;
        float2 a0 = __half22float2(h0[0]), b0 = __half22float2(h0[1]);
        float2 a1 = __half22float2(h1[0]), c1 = __half22float2(h1[1]);
        float2 a2 = __half22float2(h2[0]), c2 = __half22float2(h2[1]);
        float2 a3 = __half22float2(h3[0]), c3 = __half22float2(h3[1]);
        s.x += (a0.x + a1.x) + (a2.x + a3.x);
        s.y += (a0.y + a1.y) + (a2.y + a3.y);
        s.z += (b0.x + c1.x) + (c2.x + c3.x);
        s.w += (b0.y + c1.y) + (c2.y + c3.y);
    }
    for (; e < end; e++) {
        uint2 u = Hp[(size_t)g_col[e] * 32 + lane];
        __half2* h = (__half2*)&u;
        float2 a = __half22float2(h[0]);
        float2 b = __half22float2(h[1]);
        s.x += a.x; s.y += a.y; s.z += b.x; s.w += b.y;
    }
    float4 bb = ((const float4*)b1)[lane];
    __half2 o0 = __floats2half2_rn(fmaxf(fmaf(dvn, s.x, bb.x), 0.f),
                                   fmaxf(fmaf(dvn, s.y, bb.y), 0.f));
    __half2 o1 = __floats2half2_rn(fmaxf(fmaf(dvn, s.z, bb.z), 0.f),
                                   fmaxf(fmaf(dvn, s.w, bb.w), 0.f));
    uint2 uo; uo.x = *(unsigned*)&o0; uo.y = *(unsigned*)&o1;
    ((uint2*)g_H1h)[(size_t)node * 32 + lane] = uo;
}

// ============ GEMM2 (HMMA): Hs2 = (H1 @ W2)*dinv[row], fp16 in/out =============
__global__ void __launch_bounds__(128) gemm2h_kernel() {
    __shared__ __align__(16) __half sA[64 * 136];
    __shared__ __align__(16) __half sB[N_CLS * 136];
    __shared__ float sDv[64];
    int tid = threadIdx.x, w = tid >> 5, lane = tid & 31;
    int row0 = blockIdx.x * 64;

    // stage A: 64 rows x 128 halves = 1024 uint4
#pragma unroll
    for (int i = 0; i < 8; i++) {
        int idx = tid + i * 128;
        int r = idx >> 4, q = idx & 15;
        int row = row0 + r;
        uint4 u = make_uint4(0u, 0u, 0u, 0u);
        if (row < N_NODES)
            u = *(const uint4*)(g_H1h + (size_t)row * HID + q * 8);
        *(uint4*)&sA[r * 136 + q * 8] = u;
    }
    // stage B: 40 x 128 halves = 640 uint4
#pragma unroll
    for (int i = 0; i < 5; i++) {
        int idx = tid + i * 128;
        int n = idx >> 4, q = idx & 15;
        *(uint4*)&sB[n * 136 + q * 8] = *(const uint4*)(g_W2t + n * 128 + q * 8);
    }
    if (tid < 64) {
        int row = row0 + tid;
        sDv[tid] = (row < N_NODES) ? g_dinv[row] : 0.f;
    }
    __syncthreads();

    float acc[5][4];
#pragma unroll
    for (int nf = 0; nf < 5; nf++)
#pragma unroll
        for (int q = 0; q < 4; q++) acc[nf][q] = 0.f;

#pragma unroll
    for (int ks = 0; ks < 8; ks++) {
        uint32_t a[4];
        uint32_t addr = smem_u32(
            &sA[(w * 16 + (lane & 15)) * 136 + ks * 16 + (lane >> 4) * 8]);
        asm volatile(
            "ldmatrix.sync.aligned.m8n8.x4.shared.b16 {%0,%1,%2,%3}, [%4];"
            : "=r"(a[0]), "=r"(a[1]), "=r"(a[2]), "=r"(a[3]) : "r"(addr));
#pragma unroll
        for (int nf = 0; nf < 5; nf++) {
            uint32_t bf0, bf1;
            uint32_t baddr = smem_u32(
                &sB[(nf * 8 + (lane & 7)) * 136 + ks * 16 + ((lane >> 3) & 1) * 8]);
            asm volatile(
                "ldmatrix.sync.aligned.m8n8.x2.shared.b16 {%0,%1}, [%2];"
                : "=r"(bf0), "=r"(bf1) : "r"(baddr));
            asm volatile(
                "mma.sync.aligned.m16n8k16.row.col.f32.f16.f16.f32 "
                "{%0,%1,%2,%3}, {%4,%5,%6,%7}, {%8,%9}, {%0,%1,%2,%3};"
                : "+f"(acc[nf][0]), "+f"(acc[nf][1]), "+f"(acc[nf][2]), "+f"(acc[nf][3])
                : "r"(a[0]), "r"(a[1]), "r"(a[2]), "r"(a[3]), "r"(bf0), "r"(bf1));
        }
    }
    __syncthreads();                       // before reusing sA as C

    __half* sC = sA;                       // [64][48]
    int r0 = lane >> 2, cp = (lane & 3) * 2;
    int ra = w * 16 + r0;
    float dva = sDv[ra], dvb = sDv[ra + 8];
#pragma unroll
    for (int nf = 0; nf < 5; nf++) {
        *(__half2*)&sC[ra * 48 + nf * 8 + cp] =
            __floats2half2_rn(acc[nf][0] * dva, acc[nf][1] * dva);
        *(__half2*)&sC[(ra + 8) * 48 + nf * 8 + cp] =
            __floats2half2_rn(acc[nf][2] * dvb, acc[nf][3] * dvb);
    }
    __syncthreads();
    // store: 64 rows x 40 halves = 320 uint4
#pragma unroll
    for (int i = 0; i < 3; i++) {
        int idx = tid + i * 128;
        if (idx < 320) {
            int r = idx / 5, q = idx % 5;
            int row = row0 + r;
            if (row < N_NODES)
                *(uint4*)(g_Hs2 + (size_t)row * N_CLS + q * 8) =
                    *(uint4*)&sC[r * 48 + q * 8];
        }
    }
}

// ============ agg2: out = dinv*(Hs2[self] + sum Hs2[col]) + b2 =================
__global__ void agg2_kernel(const float* __restrict__ b2, float* __restrict__ out) {
    int warp = threadIdx.x >> 5;
    int lane = threadIdx.x & 31;
    int node = blockIdx.x * 8 + warp;
    if (node >= N_NODES || lane >= 20) return;
    int beg = g_rowptr[node], end = g_rowptr[node + 1];
    const __half2* H2 = (const __half2*)g_Hs2;
    float2 s = __half22float2(H2[(size_t)node * 20 + lane]);
    int e = beg;
    for (; e + 4 <= end; e += 4) {
        int i0 = g_col[e], i1 = g_col[e + 1], i2 = g_col[e + 2], i3 = g_col[e + 3];
        float2 a0 = __half22float2(H2[(size_t)i0 * 20 + lane]);
        float2 a1 = __half22float2(H2[(size_t)i1 * 20 + lane]);
        float2 a2 = __half22float2(H2[(size_t)i2 * 20 + lane]);
        float2 a3 = __half22float2(H2[(size_t)i3 * 20 + lane]);
        s.x += (a0.x + a1.x) + (a2.x + a3.x);
        s.y += (a0.y + a1.y) + (a2.y + a3.y);
    }
    for (; e < end; e++) {
        float2 a = __half22float2(H2[(size_t)g_col[e] * 20 + lane]);
        s.x += a.x; s.y += a.y;
    }
    float dv = g_dinv[node];
    out[(size_t)node * N_CLS + lane * 2]     = fmaf(dv, s.x, b2[lane * 2]);
    out[(size_t)node * N_CLS + lane * 2 + 1] = fmaf(dv, s.y, b2[lane * 2 + 1]);
}

// ---------------- launch ----------------
extern "C" void kernel_launch(void* const* d_in, const int* in_sizes, int n_in,
                              void* d_out, int out_size) {
    const float* x  = (const float*)d_in[0];
    const int*   ei = (const int*)  d_in[1];
    const float* W1 = (const float*)d_in[2];
    const float* b1 = (const float*)d_in[3];
    const float* W2 = (const float*)d_in[4];
    const float* b2 = (const float*)d_in[5];
    float* out = (float*)d_out;
    (void)in_sizes; (void)n_in; (void)out_size;

    prep_kernel       <<<25021, 128>>>(ei, x, W1, W2);   // count ∥ fp16 converts
    scan_reduce_kernel<<<NBLK_SCAN, 256>>>();
    scan_dist_kernel  <<<NBLK_SCAN, 1024>>>();
    fat_kernel        <<<G1_TILES * 2, 128>>>(ei);       // fill(1024e/blk) ∥ GEMM1
    agg1_kernel       <<<(N_NODES + 3) / 4, 128>>>(b1);
    gemm2h_kernel     <<<G2_TILES, 128>>>();
    agg2_kernel       <<<(N_NODES + 7) / 8, 256>>>(b2, out);
}